// round 8
// baseline (speedup 1.0000x reference)
#include <cuda_runtime.h>
#include <cuda_bf16.h>

// Problem constants (fixed by the reference)
#define M_ITEMS 20001      // emb rows / segments
#define EDIM    128
#define NE      640000     // edges (divisible by 256)

typedef unsigned long long ull;

// Scratch (device globals: no runtime allocation allowed)
__device__ __nv_bfloat16 g_itemh[M_ITEMS * EDIM]; // item_scaled in bf16 (gather table)
__device__ float g_a1[M_ITEMS];            // item_scaled . W_att[:128]  (fp32 exact)
__device__ float g_a2[M_ITEMS];            // item_scaled . W_att[128:]  (fp32 exact)
__device__ int2  g_ds[NE];                 // packed (dst, score_bits) per edge
__device__ int   g_segstart[M_ITEMS + 1];  // segment boundaries (edges sorted by src)

// ---- Blackwell packed fp32x2 FMA (SASS FFMA2; only reachable via PTX) ----
__device__ __forceinline__ void fma2(ull& d, ull a, ull b) {
    asm("fma.rn.f32x2 %0, %1, %2, %0;" : "+l"(d) : "l"(a), "l"(b));
}
__device__ __forceinline__ ull pk2(float lo, float hi) {
    ull r; asm("mov.b64 %0, {%1, %2};" : "=l"(r) : "f"(lo), "f"(hi)); return r;
}
__device__ __forceinline__ void upk2(ull v, float& lo, float& hi) {
    asm("mov.b64 {%0, %1}, %2;" : "=f"(lo), "=f"(hi) : "l"(v));
}

// ---------------------------------------------------------------------------
// K1: item_scaled = emb_mat @ W_scale + b_scale   (20001 x 128 x 128, fp32)
// 64-row tile / 256 threads / 8x4 micro-tile, inner loop in packed FFMA2:
// accumulators pair adjacent ROWS so the A-pair is a single LDS.64 from the
// transposed sA tile (zero pack cost); W columns are splat-packed (4 movs/k).
// Bit-exact fp32. Epilogue: bf16 item row + fp32 a1/a2 scalars.
// ---------------------------------------------------------------------------
__global__ void __launch_bounds__(256) k_gemm(const float* __restrict__ A,
                                              const float* __restrict__ W,
                                              const float* __restrict__ bias,
                                              const float* __restrict__ Watt) {
    __shared__ alignas(16) float sW[64 * 128];
    __shared__ alignas(16) float sA[64 * 64];   // transposed: sA[k][row]

    const int t  = threadIdx.x;
    const int tx = t & 31;          // column group: cols [4*tx, 4*tx+3]
    const int ty = t >> 5;          // row group: rows [8*ty, 8*ty+7]
    const int r0 = blockIdx.x * 64;

    // acc2[u][c] = packed (row 8ty+2u, row 8ty+2u+1) accumulator for col 4tx+c
    ull acc2[4][4];
#pragma unroll
    for (int u = 0; u < 4; ++u)
#pragma unroll
        for (int c = 0; c < 4; ++c) acc2[u][c] = 0ull;

    for (int kh = 0; kh < 2; ++kh) {
        const int k0 = kh * 64;
        // ---- load W[k0:k0+64][0:128] coalesced ----
        {
            const float4* Wg  = reinterpret_cast<const float4*>(W + (size_t)k0 * 128);
            float4*       sW4 = reinterpret_cast<float4*>(sW);
#pragma unroll
            for (int i = 0; i < 8; ++i) sW4[t + i * 256] = Wg[t + i * 256];
        }
        // ---- load A rows [r0, r0+64), k in [k0, k0+64), transposed ----
        {
            const int row  = t >> 2;               // 0..63
            const int kq   = (t & 3) * 16;         // 0,16,32,48
            const int grow = min(r0 + row, M_ITEMS - 1);
            const float4* Ag = reinterpret_cast<const float4*>(A + (size_t)grow * 128 + k0 + kq);
#pragma unroll
            for (int q = 0; q < 4; ++q) {
                float4 v = Ag[q];
                const int kk = kq + q * 4;
                sA[(kk + 0) * 64 + row] = v.x;
                sA[(kk + 1) * 64 + row] = v.y;
                sA[(kk + 2) * 64 + row] = v.z;
                sA[(kk + 3) * 64 + row] = v.w;
            }
        }
        __syncthreads();

        const float4* sW4 = reinterpret_cast<const float4*>(sW);
        const ull*    sA2 = reinterpret_cast<const ull*>(sA);     // row pairs
#pragma unroll 8
        for (int k = 0; k < 64; ++k) {
            const float4 w4 = sW4[k * 32 + tx];
            const ull wx = pk2(w4.x, w4.x);
            const ull wy = pk2(w4.y, w4.y);
            const ull wz = pk2(w4.z, w4.z);
            const ull ww = pk2(w4.w, w4.w);
            const ull a01 = sA2[k * 32 + ty * 4 + 0];   // rows 8ty+0,1
            const ull a23 = sA2[k * 32 + ty * 4 + 1];   // rows 8ty+2,3
            const ull a45 = sA2[k * 32 + ty * 4 + 2];   // rows 8ty+4,5
            const ull a67 = sA2[k * 32 + ty * 4 + 3];   // rows 8ty+6,7
            fma2(acc2[0][0], a01, wx); fma2(acc2[0][1], a01, wy);
            fma2(acc2[0][2], a01, wz); fma2(acc2[0][3], a01, ww);
            fma2(acc2[1][0], a23, wx); fma2(acc2[1][1], a23, wy);
            fma2(acc2[1][2], a23, wz); fma2(acc2[1][3], a23, ww);
            fma2(acc2[2][0], a45, wx); fma2(acc2[2][1], a45, wy);
            fma2(acc2[2][2], a45, wz); fma2(acc2[2][3], a45, ww);
            fma2(acc2[3][0], a67, wx); fma2(acc2[3][1], a67, wy);
            fma2(acc2[3][2], a67, wz); fma2(acc2[3][3], a67, ww);
        }
        __syncthreads();
    }

    const float4 b4 = reinterpret_cast<const float4*>(bias)[tx];
    const float4 w1 = reinterpret_cast<const float4*>(Watt)[tx];       // W_att[:128]
    const float4 w2 = reinterpret_cast<const float4*>(Watt)[32 + tx];  // W_att[128:]

#pragma unroll
    for (int u = 0; u < 4; ++u) {
        float lo[4], hi[4];
#pragma unroll
        for (int c = 0; c < 4; ++c) upk2(acc2[u][c], lo[c], hi[c]);
#pragma unroll
        for (int h = 0; h < 2; ++h) {
            const int row = r0 + ty * 8 + 2 * u + h;
            float4 o;
            o.x = (h ? hi[0] : lo[0]) + b4.x;
            o.y = (h ? hi[1] : lo[1]) + b4.y;
            o.z = (h ? hi[2] : lo[2]) + b4.z;
            o.w = (h ? hi[3] : lo[3]) + b4.w;
            if (row < M_ITEMS) {
                // bf16 row for the gather table (halves k_agg traffic)
                __nv_bfloat162 h0 = __float22bfloat162_rn(make_float2(o.x, o.y));
                __nv_bfloat162 h1 = __float22bfloat162_rn(make_float2(o.z, o.w));
                uint2 pk;
                pk.x = *reinterpret_cast<unsigned int*>(&h0);
                pk.y = *reinterpret_cast<unsigned int*>(&h1);
                reinterpret_cast<uint2*>(g_itemh)[(size_t)row * 32 + tx] = pk;
            }

            // fused attention scalars (fp32 exact): reduce across warp columns
            float d1 = o.x * w1.x + o.y * w1.y + o.z * w1.z + o.w * w1.w;
            float d2 = o.x * w2.x + o.y * w2.y + o.z * w2.z + o.w * w2.w;
#pragma unroll
            for (int off = 16; off; off >>= 1) {
                d1 += __shfl_xor_sync(0xFFFFFFFFu, d1, off);
                d2 += __shfl_xor_sync(0xFFFFFFFFu, d2, off);
            }
            if (tx == 0 && row < M_ITEMS) {
                g_a1[row] = d1;
                g_a2[row] = d2;
            }
        }
    }
}

// ---------------------------------------------------------------------------
// K2: fused edge pass with per-block dtype sniff.
// If the edge tensor is int64, every odd 32-bit word in this block's window
// is a zero high-half; if int32, odd words are dst indices (never all zero
// over 256 random edges). In the int32 case the sniffed word IS dst.
// ---------------------------------------------------------------------------
__global__ void __launch_bounds__(256) k_edge(const int* __restrict__ ew,
                                              const float* __restrict__ batt) {
    __shared__ unsigned int s_or[8];
    const int e    = blockIdx.x * 256 + threadIdx.x;   // NE % 256 == 0
    const int lane = threadIdx.x & 31;

    const unsigned int odd = ((const unsigned int*)ew)[2 * e + 1];
    unsigned int v = odd;
#pragma unroll
    for (int o = 16; o; o >>= 1) v |= __shfl_xor_sync(0xFFFFFFFFu, v, o);
    if (lane == 0) s_or[threadIdx.x >> 5] = v;
    __syncthreads();
    const unsigned int t = s_or[0] | s_or[1] | s_or[2] | s_or[3] |
                           s_or[4] | s_or[5] | s_or[6] | s_or[7];
    const bool is64 = (t == 0u);

    int src, dst;
    if (is64) { src = ew[4 * e]; dst = ew[4 * e + 2]; }
    else      { src = ew[2 * e]; dst = (int)odd; }

    float att = g_a1[src] + g_a2[dst] + batt[0];
    att = att > 0.f ? att : 0.2f * att;                    // leaky_relu(0.2)
    const float sc = __expf(att - 1.0f);
    g_ds[e] = make_int2(dst, __float_as_int(sc));

    // segment boundaries (race-free: disjoint ranges per thread)
    const int sprev = (e == 0) ? -1 : (is64 ? ew[4 * e - 4] : ew[2 * e - 2]);
    if (src != sprev) {
        for (int q = sprev + 1; q <= src; ++q) g_segstart[q] = e;
    }
    if (e == NE - 1) {
        for (int q = src + 1; q <= M_ITEMS; ++q) g_segstart[q] = NE;
    }
}

// ---------------------------------------------------------------------------
// K3: warp-per-segment gather-aggregate over the bf16 item table.
// Block = 64 (2 segments) to minimize intra-block straggle. Uniform 16-deep
// load batches: padded slots carry (dst=0, sc=0) from staging, so they add
// nothing and hit L1 (row 0 stays hot) -> no serial tail loop, 16 loads in
// flight per warp. Softmax normalization post-scaled. Fixed reduction
// orders -> deterministic.
// ---------------------------------------------------------------------------
__global__ void __launch_bounds__(64) k_agg(float* __restrict__ out) {
    const int seg  = blockIdx.x * 2 + (threadIdx.x >> 5);
    const int lane = threadIdx.x & 31;
    if (seg >= M_ITEMS) return;

    const int lo = __ldg(&g_segstart[seg]);
    const int hi = __ldg(&g_segstart[seg + 1]);

    const uint2* itemh = reinterpret_cast<const uint2*>(g_itemh);   // row = 32 uint2
    float4 acc = make_float4(0.f, 0.f, 0.f, 0.f);
    float  ssum = 0.f;

    for (int base = lo; base < hi; base += 32) {
        const int cnt = min(32, hi - base);
        int   dst = 0;
        float sc  = 0.f;
        if (lane < cnt) {
            const int2 ds = g_ds[base + lane];
            dst = ds.x;
            sc  = __int_as_float(ds.y);
        }
        ssum += sc;   // per-lane partial, fixed order

        for (int j = 0; j < cnt; j += 16) {   // 16 gathers in flight; tail zero-padded
            int d[16]; float c[16]; uint2 v[16];
#pragma unroll
            for (int u = 0; u < 16; ++u) {
                d[u] = __shfl_sync(0xFFFFFFFFu, dst, j + u);  // padded slots -> 0
                c[u] = __shfl_sync(0xFFFFFFFFu, sc,  j + u);  // padded slots -> 0.0
            }
#pragma unroll
            for (int u = 0; u < 16; ++u) v[u] = itemh[(size_t)d[u] * 32 + lane];
#pragma unroll
            for (int u = 0; u < 16; ++u) {
                const float2 p0 = __bfloat1622float2(*reinterpret_cast<const __nv_bfloat162*>(&v[u].x));
                const float2 p1 = __bfloat1622float2(*reinterpret_cast<const __nv_bfloat162*>(&v[u].y));
                acc.x += c[u] * p0.x; acc.y += c[u] * p0.y;
                acc.z += c[u] * p1.x; acc.w += c[u] * p1.y;
            }
        }
    }

    // warp-reduce score total (fixed order -> deterministic)
#pragma unroll
    for (int o = 16; o; o >>= 1) ssum += __shfl_xor_sync(0xFFFFFFFFu, ssum, o);
    const float inv = (hi > lo) ? 1.f / ssum : 0.f;

    float4 r;
    r.x = 1.f / (1.f + __expf(-acc.x * inv));
    r.y = 1.f / (1.f + __expf(-acc.y * inv));
    r.z = 1.f / (1.f + __expf(-acc.z * inv));
    r.w = 1.f / (1.f + __expf(-acc.w * inv));
    reinterpret_cast<float4*>(out)[(size_t)seg * 32 + lane] = r;
}

// ---------------------------------------------------------------------------
extern "C" void kernel_launch(void* const* d_in, const int* in_sizes, int n_in,
                              void* d_out, int out_size) {
    const float* emb  = (const float*)d_in[0];      // (20001, 128) f32
    const int*   edge = (const int*)d_in[1];        // (640000, 2) int (32/64-bit, sniffed)
    const float* W    = (const float*)d_in[2];      // (128, 128) f32
    const float* b    = (const float*)d_in[3];      // (128,) f32
    const float* Watt = (const float*)d_in[4];      // (256, 1) f32
    const float* batt = (const float*)d_in[5];      // (1,) f32
    float*       out  = (float*)d_out;              // (20001, 128) f32

    k_gemm<<<(M_ITEMS + 63) / 64, 256>>>(emb, W, b, Watt);
    k_edge<<<NE / 256, 256>>>(edge, batt);
    k_agg <<<(M_ITEMS + 1) / 2, 64>>>(out);
}

// round 10
// speedup vs baseline: 1.3467x; 1.3467x over previous
#include <cuda_runtime.h>
#include <cuda_bf16.h>
#include <cstdint>

// Problem constants (fixed by the reference)
#define M_ITEMS 20001      // emb rows / segments
#define EDIM    128
#define NE      640000     // edges (divisible by 256)
#define TILE_M  128        // rows per CTA in the MMA GEMM

// Scratch (device globals: no runtime allocation allowed)
__device__ __nv_bfloat16 g_itemh[M_ITEMS * EDIM]; // item_scaled in bf16 (gather table)
__device__ float g_a1[M_ITEMS];            // item_scaled . W_att[:128]
__device__ float g_a2[M_ITEMS];            // item_scaled . W_att[128:]
__device__ int2  g_ds[NE];                 // packed (dst, score_bits) per edge
__device__ int   g_segstart[M_ITEMS + 1];  // segment boundaries (edges sorted by src)

// ---------------- warp-MMA helpers (sm_80-class PTX: valid on sm_103) ------
__device__ __forceinline__ uint32_t smem_u32(const void* p) {
    uint32_t a;
    asm("{ .reg .u64 t; cvta.to.shared.u64 t, %1; cvt.u32.u64 %0, t; }" : "=r"(a) : "l"(p));
    return a;
}
// swizzle: XOR row bits (8..10) into the 16B-chunk selector (bits 4..6);
// rows are 256B, so 8 consecutive rows at the same column hit 8 distinct
// banks' chunks -> every ldmatrix phase is conflict-free.
__device__ __forceinline__ uint32_t swz(uint32_t off) {
    return off ^ (((off >> 8) & 7u) << 4);
}
__device__ __forceinline__ void ldsm_x4(uint32_t* r, uint32_t addr) {
    asm volatile("ldmatrix.sync.aligned.m8n8.x4.shared.b16 {%0,%1,%2,%3}, [%4];"
                 : "=r"(r[0]), "=r"(r[1]), "=r"(r[2]), "=r"(r[3]) : "r"(addr));
}
__device__ __forceinline__ void ldsm_x4_t(uint32_t* r, uint32_t addr) {
    asm volatile("ldmatrix.sync.aligned.m8n8.x4.trans.shared.b16 {%0,%1,%2,%3}, [%4];"
                 : "=r"(r[0]), "=r"(r[1]), "=r"(r[2]), "=r"(r[3]) : "r"(addr));
}
__device__ __forceinline__ void mma_bf16(float* c, const uint32_t* a, uint32_t b0, uint32_t b1) {
    asm volatile("mma.sync.aligned.m16n8k16.row.col.f32.bf16.bf16.f32 "
                 "{%0,%1,%2,%3}, {%4,%5,%6,%7}, {%8,%9}, {%0,%1,%2,%3};"
                 : "+f"(c[0]), "+f"(c[1]), "+f"(c[2]), "+f"(c[3])
                 : "r"(a[0]), "r"(a[1]), "r"(a[2]), "r"(a[3]), "r"(b0), "r"(b1));
}

// Dynamic smem layout: [0,512) bias, [512,1536) Watt, [2048,34816) sA bf16
// [128 rows x 256B], [34816,67584) sB bf16 [128 k-rows x 256B].
#define SM_BIAS  0
#define SM_WATT  512
#define SM_A     2048
#define SM_B     (2048 + 32768)
#define SM_TOTAL (2048 + 65536)

// ---------------------------------------------------------------------------
// K1: item_scaled = emb @ W + b via warp-level bf16 HMMA (fp32 accumulate).
// CTA = 128 rows, 256 threads (8 warps x 16 rows). B = W [K,N] row-major in
// smem; ldmatrix.trans yields col-major fragments. Epilogue: bias add, bf16
// item store, a1/a2 from fp32 accumulators via quad shuffles.
// ---------------------------------------------------------------------------
__global__ void __launch_bounds__(256) k_gemm(const float* __restrict__ A,
                                              const float* __restrict__ W,
                                              const float* __restrict__ bias,
                                              const float* __restrict__ Watt) {
    extern __shared__ unsigned char smem_raw[];
    const uint32_t sb = smem_u32(smem_raw);
    float* s_bias = reinterpret_cast<float*>(smem_raw + SM_BIAS);
    float* s_watt = reinterpret_cast<float*>(smem_raw + SM_WATT);

    const int tid  = threadIdx.x;
    const int w    = tid >> 5;
    const int lane = tid & 31;
    const int r0   = blockIdx.x * TILE_M;

    if (tid < 128) {
        s_bias[tid] = bias[tid];
        s_watt[tid] = Watt[tid];
        s_watt[tid + 128] = Watt[tid + 128];
    }

    // fill sA (A rows r0..r0+127 -> bf16) and sB (W -> bf16), swizzled
#pragma unroll
    for (int i = 0; i < 16; ++i) {
        const int idx = tid + i * 256;        // 4096 float4 groups
        const int row = idx >> 5;             // 0..127
        const int cg  = idx & 31;             // float4 group 0..31
        // A
        {
            const int gr = min(r0 + row, M_ITEMS - 1);
            const float4 v = reinterpret_cast<const float4*>(A)[(size_t)gr * 32 + cg];
            const __nv_bfloat162 h0 = __float22bfloat162_rn(make_float2(v.x, v.y));
            const __nv_bfloat162 h1 = __float22bfloat162_rn(make_float2(v.z, v.w));
            uint2 pk;
            pk.x = *reinterpret_cast<const uint32_t*>(&h0);
            pk.y = *reinterpret_cast<const uint32_t*>(&h1);
            *reinterpret_cast<uint2*>(smem_raw + SM_A + swz(row * 256 + cg * 8)) = pk;
        }
        // B = W row-major [K=128][N=128]
        {
            const float4 v = reinterpret_cast<const float4*>(W)[(size_t)row * 32 + cg];
            const __nv_bfloat162 h0 = __float22bfloat162_rn(make_float2(v.x, v.y));
            const __nv_bfloat162 h1 = __float22bfloat162_rn(make_float2(v.z, v.w));
            uint2 pk;
            pk.x = *reinterpret_cast<const uint32_t*>(&h0);
            pk.y = *reinterpret_cast<const uint32_t*>(&h1);
            *reinterpret_cast<uint2*>(smem_raw + SM_B + swz(row * 256 + cg * 8)) = pk;
        }
    }
    __syncthreads();

    // accumulators: 16 n-frags x 4 fp32
    float acc[16][4];
#pragma unroll
    for (int nf = 0; nf < 16; ++nf)
#pragma unroll
        for (int c = 0; c < 4; ++c) acc[nf][c] = 0.f;

    // A frag addr: rows w*16 + (lane&7) + ((lane>>3)&1)*8, col 16B half (lane>>4)
    const uint32_t a_row = (uint32_t)(w * 16 + (lane & 7) + ((lane >> 3) & 1) * 8);
    const uint32_t a_colh = (uint32_t)((lane >> 4) & 1) * 16;
    // B frag addr: k-rows (lane&15), n-half (lane>>4)
    const uint32_t b_krow = (uint32_t)(lane & 15);
    const uint32_t b_half = (uint32_t)((lane >> 4) & 1) * 16;

#pragma unroll
    for (int kk = 0; kk < 8; ++kk) {
        uint32_t a[4];
        ldsm_x4(a, sb + SM_A + swz(a_row * 256 + (uint32_t)kk * 32 + a_colh));
#pragma unroll
        for (int p = 0; p < 8; ++p) {
            uint32_t b[4];
            ldsm_x4_t(b, sb + SM_B + swz((kk * 16 + b_krow) * 256 + (uint32_t)p * 32 + b_half));
            mma_bf16(acc[2 * p],     a, b[0], b[1]);
            mma_bf16(acc[2 * p + 1], a, b[2], b[3]);
        }
    }

    // Epilogue. D layout m16n8: c0,c1 -> row (lane>>2), cols (lane&3)*2+{0,1};
    // c2,c3 -> row (lane>>2)+8.
    const int m_lo = r0 + w * 16 + (lane >> 2);
    const int m_hi = m_lo + 8;
    uint32_t* items32 = reinterpret_cast<uint32_t*>(g_itemh);
    float d1lo = 0.f, d2lo = 0.f, d1hi = 0.f, d2hi = 0.f;

#pragma unroll
    for (int nf = 0; nf < 16; ++nf) {
        const int col = nf * 8 + (lane & 3) * 2;
        const float bx = s_bias[col], by = s_bias[col + 1];
        const float w1x = s_watt[col], w1y = s_watt[col + 1];
        const float w2x = s_watt[128 + col], w2y = s_watt[128 + col + 1];

        const float o0 = acc[nf][0] + bx, o1 = acc[nf][1] + by;
        const float p0 = acc[nf][2] + bx, p1 = acc[nf][3] + by;
        d1lo += o0 * w1x + o1 * w1y;  d2lo += o0 * w2x + o1 * w2y;
        d1hi += p0 * w1x + p1 * w1y;  d2hi += p0 * w2x + p1 * w2y;

        const __nv_bfloat162 hlo = __float22bfloat162_rn(make_float2(o0, o1));
        const __nv_bfloat162 hhi = __float22bfloat162_rn(make_float2(p0, p1));
        if (m_lo < M_ITEMS) items32[(size_t)m_lo * 64 + (col >> 1)] = *reinterpret_cast<const uint32_t*>(&hlo);
        if (m_hi < M_ITEMS) items32[(size_t)m_hi * 64 + (col >> 1)] = *reinterpret_cast<const uint32_t*>(&hhi);
    }

    // quad-reduce (lanes sharing a row): fixed order -> deterministic
#pragma unroll
    for (int off = 1; off <= 2; off <<= 1) {
        d1lo += __shfl_xor_sync(0xFFFFFFFFu, d1lo, off);
        d2lo += __shfl_xor_sync(0xFFFFFFFFu, d2lo, off);
        d1hi += __shfl_xor_sync(0xFFFFFFFFu, d1hi, off);
        d2hi += __shfl_xor_sync(0xFFFFFFFFu, d2hi, off);
    }
    if ((lane & 3) == 0) {
        if (m_lo < M_ITEMS) { g_a1[m_lo] = d1lo; g_a2[m_lo] = d2lo; }
        if (m_hi < M_ITEMS) { g_a1[m_hi] = d1hi; g_a2[m_hi] = d2hi; }
    }
}

// ---------------------------------------------------------------------------
// K2: fused edge pass with per-block dtype sniff (int64 high-halves are 0).
// ---------------------------------------------------------------------------
__global__ void __launch_bounds__(256) k_edge(const int* __restrict__ ew,
                                              const float* __restrict__ batt) {
    __shared__ unsigned int s_or[8];
    const int e    = blockIdx.x * 256 + threadIdx.x;   // NE % 256 == 0
    const int lane = threadIdx.x & 31;

    const unsigned int odd = ((const unsigned int*)ew)[2 * e + 1];
    unsigned int v = odd;
#pragma unroll
    for (int o = 16; o; o >>= 1) v |= __shfl_xor_sync(0xFFFFFFFFu, v, o);
    if (lane == 0) s_or[threadIdx.x >> 5] = v;
    __syncthreads();
    const unsigned int t = s_or[0] | s_or[1] | s_or[2] | s_or[3] |
                           s_or[4] | s_or[5] | s_or[6] | s_or[7];
    const bool is64 = (t == 0u);

    int src, dst;
    if (is64) { src = ew[4 * e]; dst = ew[4 * e + 2]; }
    else      { src = ew[2 * e]; dst = (int)odd; }

    float att = g_a1[src] + g_a2[dst] + batt[0];
    att = att > 0.f ? att : 0.2f * att;                    // leaky_relu(0.2)
    const float sc = __expf(att - 1.0f);
    g_ds[e] = make_int2(dst, __float_as_int(sc));

    // segment boundaries (race-free: disjoint ranges per thread)
    const int sprev = (e == 0) ? -1 : (is64 ? ew[4 * e - 4] : ew[2 * e - 2]);
    if (src != sprev) {
        for (int q = sprev + 1; q <= src; ++q) g_segstart[q] = e;
    }
    if (e == NE - 1) {
        for (int q = src + 1; q <= M_ITEMS; ++q) g_segstart[q] = NE;
    }
}

// ---------------------------------------------------------------------------
// K3: warp-per-segment gather-aggregate over the bf16 item table.
// Block = 64 (2 segments). Uniform 16-deep load batches, zero-padded tail,
// post-scaled softmax. Fixed reduction orders -> deterministic.
// ---------------------------------------------------------------------------
__global__ void __launch_bounds__(64) k_agg(float* __restrict__ out) {
    const int seg  = blockIdx.x * 2 + (threadIdx.x >> 5);
    const int lane = threadIdx.x & 31;
    if (seg >= M_ITEMS) return;

    const int lo = __ldg(&g_segstart[seg]);
    const int hi = __ldg(&g_segstart[seg + 1]);

    const uint2* itemh = reinterpret_cast<const uint2*>(g_itemh);   // row = 32 uint2
    float4 acc = make_float4(0.f, 0.f, 0.f, 0.f);
    float  ssum = 0.f;

    for (int base = lo; base < hi; base += 32) {
        const int cnt = min(32, hi - base);
        int   dst = 0;
        float sc  = 0.f;
        if (lane < cnt) {
            const int2 ds = g_ds[base + lane];
            dst = ds.x;
            sc  = __int_as_float(ds.y);
        }
        ssum += sc;   // per-lane partial, fixed order

        for (int j = 0; j < cnt; j += 16) {   // 16 gathers in flight; tail zero-padded
            int d[16]; float c[16]; uint2 v[16];
#pragma unroll
            for (int u = 0; u < 16; ++u) {
                d[u] = __shfl_sync(0xFFFFFFFFu, dst, j + u);  // padded slots -> 0
                c[u] = __shfl_sync(0xFFFFFFFFu, sc,  j + u);  // padded slots -> 0.0
            }
#pragma unroll
            for (int u = 0; u < 16; ++u) v[u] = itemh[(size_t)d[u] * 32 + lane];
#pragma unroll
            for (int u = 0; u < 16; ++u) {
                const float2 p0 = __bfloat1622float2(*reinterpret_cast<const __nv_bfloat162*>(&v[u].x));
                const float2 p1 = __bfloat1622float2(*reinterpret_cast<const __nv_bfloat162*>(&v[u].y));
                acc.x += c[u] * p0.x; acc.y += c[u] * p0.y;
                acc.z += c[u] * p1.x; acc.w += c[u] * p1.y;
            }
        }
    }

    // warp-reduce score total (fixed order -> deterministic)
#pragma unroll
    for (int o = 16; o; o >>= 1) ssum += __shfl_xor_sync(0xFFFFFFFFu, ssum, o);
    const float inv = (hi > lo) ? 1.f / ssum : 0.f;

    float4 r;
    r.x = 1.f / (1.f + __expf(-acc.x * inv));
    r.y = 1.f / (1.f + __expf(-acc.y * inv));
    r.z = 1.f / (1.f + __expf(-acc.z * inv));
    r.w = 1.f / (1.f + __expf(-acc.w * inv));
    reinterpret_cast<float4*>(out)[(size_t)seg * 32 + lane] = r;
}

// ---------------------------------------------------------------------------
extern "C" void kernel_launch(void* const* d_in, const int* in_sizes, int n_in,
                              void* d_out, int out_size) {
    const float* emb  = (const float*)d_in[0];      // (20001, 128) f32
    const int*   edge = (const int*)d_in[1];        // (640000, 2) int (32/64-bit, sniffed)
    const float* W    = (const float*)d_in[2];      // (128, 128) f32
    const float* b    = (const float*)d_in[3];      // (128,) f32
    const float* Watt = (const float*)d_in[4];      // (256, 1) f32
    const float* batt = (const float*)d_in[5];      // (1,) f32
    float*       out  = (float*)d_out;              // (20001, 128) f32

    // attribute setter (immediate API, not a stream op; no allocation)
    cudaFuncSetAttribute(k_gemm, cudaFuncAttributeMaxDynamicSharedMemorySize, SM_TOTAL);

    k_gemm<<<(M_ITEMS + TILE_M - 1) / TILE_M, 256, SM_TOTAL>>>(emb, W, b, Watt); // 157 CTAs
    k_edge<<<NE / 256, 256>>>(edge, batt);
    k_agg <<<(M_ITEMS + 1) / 2, 64>>>(out);
}

// round 11
// speedup vs baseline: 1.5797x; 1.1730x over previous
#include <cuda_runtime.h>
#include <cuda_bf16.h>
#include <cstdint>

// Problem constants (fixed by the reference)
#define M_ITEMS 20001      // emb rows / segments
#define EDIM    128
#define NE      640000     // edges (divisible by 256)
#define TILE_M  64         // rows per CTA in the MMA GEMM

// Scratch (device globals: no runtime allocation allowed)
__device__ __nv_bfloat16 g_itemh[M_ITEMS * EDIM]; // item_scaled in bf16 (gather table)
__device__ float g_a1[M_ITEMS];            // item_scaled . W_att[:128]
__device__ float g_a2[M_ITEMS];            // item_scaled . W_att[128:]
__device__ int2  g_ds[NE];                 // packed (dst, score_bits) per edge
__device__ int   g_segstart[M_ITEMS + 1];  // segment boundaries (edges sorted by src)

// ---------------- warp-MMA helpers (sm_80-class PTX: valid on sm_103) ------
__device__ __forceinline__ uint32_t smem_u32(const void* p) {
    uint32_t a;
    asm("{ .reg .u64 t; cvta.to.shared.u64 t, %1; cvt.u32.u64 %0, t; }" : "=r"(a) : "l"(p));
    return a;
}
// swizzle: XOR row bits (8..10) into the 16B-chunk selector (bits 4..6);
// rows are 256B, so 8 consecutive rows at the same column hit 8 distinct
// banks' chunks -> every ldmatrix phase is conflict-free.
__device__ __forceinline__ uint32_t swz(uint32_t off) {
    return off ^ (((off >> 8) & 7u) << 4);
}
__device__ __forceinline__ void ldsm_x4(uint32_t* r, uint32_t addr) {
    asm volatile("ldmatrix.sync.aligned.m8n8.x4.shared.b16 {%0,%1,%2,%3}, [%4];"
                 : "=r"(r[0]), "=r"(r[1]), "=r"(r[2]), "=r"(r[3]) : "r"(addr));
}
__device__ __forceinline__ void ldsm_x4_t(uint32_t* r, uint32_t addr) {
    asm volatile("ldmatrix.sync.aligned.m8n8.x4.trans.shared.b16 {%0,%1,%2,%3}, [%4];"
                 : "=r"(r[0]), "=r"(r[1]), "=r"(r[2]), "=r"(r[3]) : "r"(addr));
}
__device__ __forceinline__ void mma_bf16(float* c, const uint32_t* a, uint32_t b0, uint32_t b1) {
    asm volatile("mma.sync.aligned.m16n8k16.row.col.f32.bf16.bf16.f32 "
                 "{%0,%1,%2,%3}, {%4,%5,%6,%7}, {%8,%9}, {%0,%1,%2,%3};"
                 : "+f"(c[0]), "+f"(c[1]), "+f"(c[2]), "+f"(c[3])
                 : "r"(a[0]), "r"(a[1]), "r"(a[2]), "r"(a[3]), "r"(b0), "r"(b1));
}

// Dynamic smem layout: [0,512) bias, [512,1536) Watt, [2048,18432) sA bf16
// [64 rows x 256B], [18432,51200) sB bf16 [128 k-rows x 256B].
#define SM_BIAS  0
#define SM_WATT  512
#define SM_A     2048
#define SM_B     (2048 + 16384)
#define SM_TOTAL (2048 + 16384 + 32768)

// ---------------------------------------------------------------------------
// K1: item_scaled = emb @ W + b via warp-level bf16 HMMA (fp32 accumulate).
// CTA = 64 rows, 128 threads (4 warps x 16 rows, full N per warp). 50KB smem
// -> 4 CTAs/SM, 313 CTAs: fill/MMA latency overlapped across CTAs.
// ---------------------------------------------------------------------------
__global__ void __launch_bounds__(128) k_gemm(const float* __restrict__ A,
                                              const float* __restrict__ W,
                                              const float* __restrict__ bias,
                                              const float* __restrict__ Watt) {
    extern __shared__ unsigned char smem_raw[];
    const uint32_t sb = smem_u32(smem_raw);
    float* s_bias = reinterpret_cast<float*>(smem_raw + SM_BIAS);
    float* s_watt = reinterpret_cast<float*>(smem_raw + SM_WATT);

    const int tid  = threadIdx.x;
    const int w    = tid >> 5;
    const int lane = tid & 31;
    const int r0   = blockIdx.x * TILE_M;

    s_bias[tid] = bias[tid];
    s_watt[tid] = Watt[tid];
    s_watt[tid + 128] = Watt[tid + 128];

    // fill sA (A rows r0..r0+63 -> bf16): 2048 float4 groups
#pragma unroll
    for (int i = 0; i < 16; ++i) {
        const int idx = tid + i * 128;
        const int row = idx >> 5;             // 0..63
        const int cg  = idx & 31;             // float4 group
        const int gr  = min(r0 + row, M_ITEMS - 1);
        const float4 v = reinterpret_cast<const float4*>(A)[(size_t)gr * 32 + cg];
        const __nv_bfloat162 h0 = __float22bfloat162_rn(make_float2(v.x, v.y));
        const __nv_bfloat162 h1 = __float22bfloat162_rn(make_float2(v.z, v.w));
        uint2 pk;
        pk.x = *reinterpret_cast<const uint32_t*>(&h0);
        pk.y = *reinterpret_cast<const uint32_t*>(&h1);
        *reinterpret_cast<uint2*>(smem_raw + SM_A + swz(row * 256 + cg * 8)) = pk;
    }
    // fill sB (W row-major [K=128][N=128] -> bf16): 4096 float4 groups
#pragma unroll
    for (int i = 0; i < 32; ++i) {
        const int idx = tid + i * 128;
        const int row = idx >> 5;             // k row 0..127
        const int cg  = idx & 31;
        const float4 v = reinterpret_cast<const float4*>(W)[(size_t)row * 32 + cg];
        const __nv_bfloat162 h0 = __float22bfloat162_rn(make_float2(v.x, v.y));
        const __nv_bfloat162 h1 = __float22bfloat162_rn(make_float2(v.z, v.w));
        uint2 pk;
        pk.x = *reinterpret_cast<const uint32_t*>(&h0);
        pk.y = *reinterpret_cast<const uint32_t*>(&h1);
        *reinterpret_cast<uint2*>(smem_raw + SM_B + swz(row * 256 + cg * 8)) = pk;
    }
    __syncthreads();

    // accumulators: 16 n-frags x 4 fp32
    float acc[16][4];
#pragma unroll
    for (int nf = 0; nf < 16; ++nf)
#pragma unroll
        for (int c = 0; c < 4; ++c) acc[nf][c] = 0.f;

    const uint32_t a_row  = (uint32_t)(w * 16 + (lane & 7) + ((lane >> 3) & 1) * 8);
    const uint32_t a_colh = (uint32_t)((lane >> 4) & 1) * 16;
    const uint32_t b_krow = (uint32_t)(lane & 15);
    const uint32_t b_half = (uint32_t)((lane >> 4) & 1) * 16;

#pragma unroll
    for (int kk = 0; kk < 8; ++kk) {
        uint32_t a[4];
        ldsm_x4(a, sb + SM_A + swz(a_row * 256 + (uint32_t)kk * 32 + a_colh));
#pragma unroll
        for (int p = 0; p < 8; ++p) {
            uint32_t b[4];
            ldsm_x4_t(b, sb + SM_B + swz((kk * 16 + b_krow) * 256 + (uint32_t)p * 32 + b_half));
            mma_bf16(acc[2 * p],     a, b[0], b[1]);
            mma_bf16(acc[2 * p + 1], a, b[2], b[3]);
        }
    }

    // Epilogue. D layout m16n8: c0,c1 -> row (lane>>2); c2,c3 -> row +8.
    const int m_lo = r0 + w * 16 + (lane >> 2);
    const int m_hi = m_lo + 8;
    uint32_t* items32 = reinterpret_cast<uint32_t*>(g_itemh);
    float d1lo = 0.f, d2lo = 0.f, d1hi = 0.f, d2hi = 0.f;

#pragma unroll
    for (int nf = 0; nf < 16; ++nf) {
        const int col = nf * 8 + (lane & 3) * 2;
        const float bx = s_bias[col], by = s_bias[col + 1];
        const float w1x = s_watt[col], w1y = s_watt[col + 1];
        const float w2x = s_watt[128 + col], w2y = s_watt[128 + col + 1];

        const float o0 = acc[nf][0] + bx, o1 = acc[nf][1] + by;
        const float p0 = acc[nf][2] + bx, p1 = acc[nf][3] + by;
        d1lo += o0 * w1x + o1 * w1y;  d2lo += o0 * w2x + o1 * w2y;
        d1hi += p0 * w1x + p1 * w1y;  d2hi += p0 * w2x + p1 * w2y;

        const __nv_bfloat162 hlo = __float22bfloat162_rn(make_float2(o0, o1));
        const __nv_bfloat162 hhi = __float22bfloat162_rn(make_float2(p0, p1));
        if (m_lo < M_ITEMS) items32[(size_t)m_lo * 64 + (col >> 1)] = *reinterpret_cast<const uint32_t*>(&hlo);
        if (m_hi < M_ITEMS) items32[(size_t)m_hi * 64 + (col >> 1)] = *reinterpret_cast<const uint32_t*>(&hhi);
    }

    // quad-reduce (lanes sharing a row): fixed order -> deterministic
#pragma unroll
    for (int off = 1; off <= 2; off <<= 1) {
        d1lo += __shfl_xor_sync(0xFFFFFFFFu, d1lo, off);
        d2lo += __shfl_xor_sync(0xFFFFFFFFu, d2lo, off);
        d1hi += __shfl_xor_sync(0xFFFFFFFFu, d1hi, off);
        d2hi += __shfl_xor_sync(0xFFFFFFFFu, d2hi, off);
    }
    if ((lane & 3) == 0) {
        if (m_lo < M_ITEMS) { g_a1[m_lo] = d1lo; g_a2[m_lo] = d2lo; }
        if (m_hi < M_ITEMS) { g_a1[m_hi] = d1hi; g_a2[m_hi] = d2hi; }
    }
}

// ---------------------------------------------------------------------------
// K2: fused edge pass with per-block dtype sniff (int64 high-halves are 0).
// ---------------------------------------------------------------------------
__global__ void __launch_bounds__(256) k_edge(const int* __restrict__ ew,
                                              const float* __restrict__ batt) {
    __shared__ unsigned int s_or[8];
    const int e    = blockIdx.x * 256 + threadIdx.x;   // NE % 256 == 0
    const int lane = threadIdx.x & 31;

    const unsigned int odd = ((const unsigned int*)ew)[2 * e + 1];
    unsigned int v = odd;
#pragma unroll
    for (int o = 16; o; o >>= 1) v |= __shfl_xor_sync(0xFFFFFFFFu, v, o);
    if (lane == 0) s_or[threadIdx.x >> 5] = v;
    __syncthreads();
    const unsigned int t = s_or[0] | s_or[1] | s_or[2] | s_or[3] |
                           s_or[4] | s_or[5] | s_or[6] | s_or[7];
    const bool is64 = (t == 0u);

    int src, dst;
    if (is64) { src = ew[4 * e]; dst = ew[4 * e + 2]; }
    else      { src = ew[2 * e]; dst = (int)odd; }

    float att = g_a1[src] + g_a2[dst] + batt[0];
    att = att > 0.f ? att : 0.2f * att;                    // leaky_relu(0.2)
    const float sc = __expf(att - 1.0f);
    g_ds[e] = make_int2(dst, __float_as_int(sc));

    // segment boundaries (race-free: disjoint ranges per thread)
    const int sprev = (e == 0) ? -1 : (is64 ? ew[4 * e - 4] : ew[2 * e - 2]);
    if (src != sprev) {
        for (int q = sprev + 1; q <= src; ++q) g_segstart[q] = e;
    }
    if (e == NE - 1) {
        for (int q = src + 1; q <= M_ITEMS; ++q) g_segstart[q] = NE;
    }
}

// ---------------------------------------------------------------------------
// K3: warp-per-segment gather-aggregate, 16-lanes-per-edge LDG.128.
// A bf16 row = 256B = 16 x uint4: lanes 0..15 cover edge pair-member 0,
// lanes 16..31 cover pair-member 1 -> one LDG.128 gathers 2 edges per warp.
// bf16->f32 via exact shifts; 32-bit offsets only; 8 loads in flight/lane
// (16 edges/warp). Pair halves combined with one shfl_xor (fixed order).
// Zero-padded staging kills the tail loop. Deterministic.
// ---------------------------------------------------------------------------
__global__ void __launch_bounds__(64) k_agg(float* __restrict__ out) {
    const int seg  = blockIdx.x * 2 + (threadIdx.x >> 5);
    const int lane = threadIdx.x & 31;
    if (seg >= M_ITEMS) return;

    const int lo = __ldg(&g_segstart[seg]);
    const int hi = __ldg(&g_segstart[seg + 1]);
    const int eh = lane >> 4;        // which edge of the pair (0/1)
    const int lq = lane & 15;        // 16B chunk within the 256B row

    const uint4* itemv = reinterpret_cast<const uint4*>(g_itemh);   // row = 16 uint4
    float acc[8];
#pragma unroll
    for (int q = 0; q < 8; ++q) acc[q] = 0.f;
    float ssum = 0.f;

    for (int base = lo; base < hi; base += 32) {
        const int cnt = min(32, hi - base);
        int   dst = 0;
        float sc  = 0.f;
        if (lane < cnt) {
            const int2 ds = g_ds[base + lane];
            dst = ds.x;
            sc  = __int_as_float(ds.y);
        }
        ssum += sc;   // per-lane partial, fixed order

        for (int j = 0; j < cnt; j += 16) {   // 16 edges per batch, zero-padded
            int d[8]; float c[8]; uint4 v[8];
#pragma unroll
            for (int u = 0; u < 8; ++u) {
                d[u] = __shfl_sync(0xFFFFFFFFu, dst, j + 2 * u + eh);  // padded -> 0
                c[u] = __shfl_sync(0xFFFFFFFFu, sc,  j + 2 * u + eh);  // padded -> 0.0
            }
#pragma unroll
            for (int u = 0; u < 8; ++u) v[u] = itemv[d[u] * 16 + lq]; // 32-bit offset
#pragma unroll
            for (int u = 0; u < 8; ++u) {
                const uint32_t* pv = reinterpret_cast<const uint32_t*>(&v[u]);
#pragma unroll
                for (int q = 0; q < 4; ++q) {
                    const float flo = __uint_as_float(pv[q] << 16);          // exact
                    const float fhi = __uint_as_float(pv[q] & 0xffff0000u);  // exact
                    acc[2 * q]     += c[u] * flo;
                    acc[2 * q + 1] += c[u] * fhi;
                }
            }
        }
    }

    // combine pair halves (fixed order) + score total reduce
#pragma unroll
    for (int q = 0; q < 8; ++q) acc[q] += __shfl_xor_sync(0xFFFFFFFFu, acc[q], 16);
#pragma unroll
    for (int o = 16; o; o >>= 1) ssum += __shfl_xor_sync(0xFFFFFFFFu, ssum, o);
    const float inv = (hi > lo) ? 1.f / ssum : 0.f;

    // lane writes its float4: cols lq*8 + eh*4 .. +3
    float4 r;
    r.x = 1.f / (1.f + __expf(-acc[eh * 4 + 0] * inv));
    r.y = 1.f / (1.f + __expf(-acc[eh * 4 + 1] * inv));
    r.z = 1.f / (1.f + __expf(-acc[eh * 4 + 2] * inv));
    r.w = 1.f / (1.f + __expf(-acc[eh * 4 + 3] * inv));
    reinterpret_cast<float4*>(out)[(size_t)seg * 32 + lq * 2 + eh] = r;
}

// ---------------------------------------------------------------------------
extern "C" void kernel_launch(void* const* d_in, const int* in_sizes, int n_in,
                              void* d_out, int out_size) {
    const float* emb  = (const float*)d_in[0];      // (20001, 128) f32
    const int*   edge = (const int*)d_in[1];        // (640000, 2) int (32/64-bit, sniffed)
    const float* W    = (const float*)d_in[2];      // (128, 128) f32
    const float* b    = (const float*)d_in[3];      // (128,) f32
    const float* Watt = (const float*)d_in[4];      // (256, 1) f32
    const float* batt = (const float*)d_in[5];      // (1,) f32
    float*       out  = (float*)d_out;              // (20001, 128) f32

    // attribute setter (immediate API, not a stream op; no allocation)
    cudaFuncSetAttribute(k_gemm, cudaFuncAttributeMaxDynamicSharedMemorySize, SM_TOTAL);

    k_gemm<<<(M_ITEMS + TILE_M - 1) / TILE_M, 128, SM_TOTAL>>>(emb, W, b, Watt); // 313 CTAs
    k_edge<<<NE / 256, 256>>>(edge, batt);
    k_agg <<<(M_ITEMS + 1) / 2, 64>>>(out);
}